// round 16
// baseline (speedup 1.0000x reference)
#include <cuda_runtime.h>
#include <cuda_fp16.h>

namespace {

constexpr int kNodes = 50000;
constexpr int kEdges = 800000;
constexpr int kCap   = 96;   // per-node adjacency capacity (Poisson(16) => never hit)

// Scratch (allocation-free __device__ globals; 16B-aligned types where needed).
__device__ float4 g_xc [kNodes * 32];   // fp32 normalized caps (dim-ordered rows)
__device__ uint4  g_xch[kNodes * 16];   // fp16 caps, dim-ordered: 256B/node, uint4 #h = dims [8h,8h+8)
__device__ float4 g_u  [kNodes * 32];   // routing state
__device__ int    g_count[kNodes];      // in-degree (built per replay)
__device__ int    g_adj  [kNodes * kCap];  // bucketed adjacency: sources per target
__device__ int    g_is_i32;             // edge_index dtype flag

__device__ __forceinline__ float group4_sum(float v) {
    v += __shfl_xor_sync(0xffffffffu, v, 1);
    v += __shfl_xor_sync(0xffffffffu, v, 2);
    return v;
}

__device__ __forceinline__ int load_idx(const void* ei, long long off) {
    if (g_is_i32) return ((const int*)ei)[off];
    return (int)((const long long*)ei)[off];
}

// ---- preprocessing ----

// Zero per-node degree counters; block 0 / warp 0 also detects index dtype
// (int64 nonneg values < 2^31 have zero high words).
__global__ void zero_detect_kernel(const unsigned int* __restrict__ w) {
    int i = blockIdx.x * blockDim.x + threadIdx.x;
    if (i < kNodes) g_count[i] = 0;
    if (blockIdx.x == 0 && threadIdx.x < 32) {
        unsigned int acc = 0;
        for (int k = threadIdx.x; k < 1024; k += 32) acc |= w[2 * k + 1];
        #pragma unroll
        for (int d = 1; d < 32; d <<= 1) acc |= __shfl_xor_sync(0xffffffffu, acc, d);
        if (threadIdx.x == 0) g_is_i32 = (acc != 0) ? 1 : 0;
    }
}

// Direct scatter into fixed-capacity per-target buckets.
__global__ void fill_adj_kernel(const void* __restrict__ ei) {
    int e = blockIdx.x * blockDim.x + threadIdx.x;
    if (e >= kEdges) return;
    int s = load_idx(ei, e);
    int g = load_idx(ei, (long long)kEdges + e);
    int pos = atomicAdd(&g_count[g], 1);
    if (pos < kCap) g_adj[g * kCap + pos] = s;
}

// ---- compute ----

// xc = l2norm_per_capsule(x); write fp32 + fp16 (dim-ordered) copies.
// One warp per node; lane t owns dims [4t, 4t+4).
__global__ void __launch_bounds__(256) init_kernel(const float* __restrict__ x) {
    int gid  = blockIdx.x * blockDim.x + threadIdx.x;
    int node = gid >> 5;
    if (node >= kNodes) return;
    int t   = gid & 31;
    int idx = node * 32 + t;

    float4 v = reinterpret_cast<const float4*>(x)[idx];
    float ss = group4_sum(v.x * v.x + v.y * v.y + v.z * v.z + v.w * v.w);
    float s  = 1.0f / fmaxf(sqrtf(ss), 1e-12f);
    v.x *= s; v.y *= s; v.z *= s; v.w *= s;
    g_xc[idx] = v;

    // fp16 copy, natural dim order: dims [4t,4t+4) -> 8 bytes at uint2-slot t.
    half2 a = __floats2half2_rn(v.x, v.y);
    half2 b = __floats2half2_rn(v.z, v.w);
    uint2 w;
    w.x = *reinterpret_cast<const unsigned int*>(&a);
    w.y = *reinterpret_cast<const unsigned int*>(&b);
    reinterpret_cast<uint2*>(g_xch)[node * 32 + t] = w;
}

// One routing iteration fused per node: warp n owns target node n.
// 16 lanes per edge: lanes [0:16) = edge i, lanes [16:32) = edge i+1 (same node
// => no pairing imbalance). Lane h = lane&15 owns dims [8h, 8h+8); capsule
// c = h>>1 (2 lanes/capsule). Per 2-edge iteration: dot reduce = 1 shfl,
// softmax over 8 caps = 3 shfls, 1 exp, 1 div — ~2x fewer issue slots than the
// 2-chain warp-per-edge-row loop. Halves merge acc once per node at the tail.
// No max-subtract: capsules are unit vectors => p in [-1,1].
template <bool FIRST, bool WRITE_OUT>
__global__ void __launch_bounds__(256, 6) route_kernel(float* __restrict__ out) {
    int gid  = blockIdx.x * blockDim.x + threadIdx.x;
    int node = gid >> 5;
    if (node >= kNodes) return;
    int lane = threadIdx.x & 31;
    int h    = lane & 15;
    int half = lane >> 4;

    // u slice dims [8h, 8h+8): float4 slots node*32 + 2h, +1 (halves broadcast).
    const float4* ub = (FIRST ? g_xc : g_u) + node * 32 + h * 2;
    float4 ua = ub[0];
    float4 uc = ub[1];

    const int* adj = g_adj + node * kCap;
    int deg = min(g_count[node], kCap);

    float4 aA = make_float4(0.f, 0.f, 0.f, 0.f);
    float4 aB = make_float4(0.f, 0.f, 0.f, 0.f);

    for (int i = 0; i < deg; i += 2) {
        int  j     = i + half;
        bool valid = j < deg;                 // uniform within each half
        int  s     = adj[valid ? j : i];

        uint4 zp = g_xch[s * 16 + h];         // 16B: fp16 dims [8h, 8h+8)
        float2 f0 = __half22float2(*reinterpret_cast<const half2*>(&zp.x));
        float2 f1 = __half22float2(*reinterpret_cast<const half2*>(&zp.y));
        float2 f2 = __half22float2(*reinterpret_cast<const half2*>(&zp.z));
        float2 f3 = __half22float2(*reinterpret_cast<const half2*>(&zp.w));

        float d = f0.x * ua.x + f0.y * ua.y + f1.x * ua.z + f1.y * ua.w
                + f2.x * uc.x + f2.y * uc.y + f3.x * uc.z + f3.y * uc.w;
        d += __shfl_xor_sync(0xffffffffu, d, 1);        // capsule dot (2 lanes/cap)

        float e = __expf(d);
        float q = e;
        q += __shfl_xor_sync(0xffffffffu, q, 2);
        q += __shfl_xor_sync(0xffffffffu, q, 4);
        q += __shfl_xor_sync(0xffffffffu, q, 8);        // sum over 8 capsules
        float w = valid ? __fdividef(e, q) : 0.f;

        aA.x += f0.x * w; aA.y += f0.y * w; aA.z += f1.x * w; aA.w += f1.y * w;
        aB.x += f2.x * w; aB.y += f2.y * w; aB.z += f3.x * w; aB.w += f3.y * w;
    }

    // Merge even/odd edge partials across halves (lane h <-> lane h+16).
    aA.x += __shfl_xor_sync(0xffffffffu, aA.x, 16);
    aA.y += __shfl_xor_sync(0xffffffffu, aA.y, 16);
    aA.z += __shfl_xor_sync(0xffffffffu, aA.z, 16);
    aA.w += __shfl_xor_sync(0xffffffffu, aA.w, 16);
    aB.x += __shfl_xor_sync(0xffffffffu, aB.x, 16);
    aB.y += __shfl_xor_sync(0xffffffffu, aB.y, 16);
    aB.z += __shfl_xor_sync(0xffffffffu, aB.z, 16);
    aB.w += __shfl_xor_sync(0xffffffffu, aB.w, 16);

    // Residual + per-capsule l2norm (capsule = 2 lanes -> xor1 reduce).
    float4 cA, cB;
    if (FIRST) { cA = ua; cB = uc; }
    else {
        const float4* cb = g_xc + node * 32 + h * 2;
        cA = cb[0]; cB = cb[1];
    }
    float4 vA = make_float4(aA.x + cA.x, aA.y + cA.y, aA.z + cA.z, aA.w + cA.w);
    float4 vB = make_float4(aB.x + cB.x, aB.y + cB.y, aB.z + cB.z, aB.w + cB.w);

    float ss = vA.x * vA.x + vA.y * vA.y + vA.z * vA.z + vA.w * vA.w
             + vB.x * vB.x + vB.y * vB.y + vB.z * vB.z + vB.w * vB.w;
    ss += __shfl_xor_sync(0xffffffffu, ss, 1);
    float sc = 1.0f / fmaxf(sqrtf(ss), 1e-12f);

    if (half == 0) {   // halves hold identical results; one writer
        float4* dst = (WRITE_OUT ? reinterpret_cast<float4*>(out) : g_u) + node * 32 + h * 2;
        dst[0] = make_float4(vA.x * sc, vA.y * sc, vA.z * sc, vA.w * sc);
        dst[1] = make_float4(vB.x * sc, vB.y * sc, vB.z * sc, vB.w * sc);
    }
}

}  // namespace

extern "C" void kernel_launch(void* const* d_in, const int* in_sizes, int n_in,
                              void* d_out, int out_size) {
    const float* x  = (const float*)d_in[0];
    const void*  ei = d_in[1];   // [2, E], int32 or int64 (detected on-device)
    float* out = (float*)d_out;

    const int nodeBlocks = (kNodes * 32 + 255) / 256;
    const int edgeBlocks = (kEdges + 255) / 256;

    zero_detect_kernel<<<(kNodes + 255) / 256, 256>>>((const unsigned int*)ei);
    fill_adj_kernel<<<edgeBlocks, 256>>>(ei);
    init_kernel<<<nodeBlocks, 256>>>(x);

    route_kernel<true,  false><<<nodeBlocks, 256>>>(nullptr);
    route_kernel<false, false><<<nodeBlocks, 256>>>(nullptr);
    route_kernel<false, true ><<<nodeBlocks, 256>>>(out);
}

// round 17
// speedup vs baseline: 1.0277x; 1.0277x over previous
#include <cuda_runtime.h>
#include <cuda_fp16.h>

namespace {

constexpr int kNodes = 50000;
constexpr int kEdges = 800000;
constexpr int kCap   = 96;   // per-node adjacency capacity (Poisson(16) => never hit)

// Scratch (allocation-free __device__ globals; 16B-aligned types where needed).
__device__ float4 g_xc [kNodes * 32];   // fp32 normalized caps
__device__ uint2  g_xch[kNodes * 32];   // fp16 copy: lane t's 4 dims as 2x half2
__device__ float4 g_u  [kNodes * 32];   // routing state
__device__ int    g_count[kNodes];      // in-degree (built per replay)
__device__ int    g_adj  [kNodes * kCap];  // bucketed adjacency: PRE-SCALED src*32
__device__ int    g_is_i32;             // edge_index dtype flag

__device__ __forceinline__ float group4_sum(float v) {
    v += __shfl_xor_sync(0xffffffffu, v, 1);
    v += __shfl_xor_sync(0xffffffffu, v, 2);
    return v;
}

__device__ __forceinline__ float cap_sum(float v) {
    v += __shfl_xor_sync(0xffffffffu, v, 4);
    v += __shfl_xor_sync(0xffffffffu, v, 8);
    v += __shfl_xor_sync(0xffffffffu, v, 16);
    return v;
}

__device__ __forceinline__ int load_idx(const void* ei, long long off) {
    if (g_is_i32) return ((const int*)ei)[off];
    return (int)((const long long*)ei)[off];
}

__device__ __forceinline__ float4 load_z_h(int idx) {
    uint2 w = g_xch[idx];
    float2 a = __half22float2(*reinterpret_cast<const half2*>(&w.x));
    float2 b = __half22float2(*reinterpret_cast<const half2*>(&w.y));
    return make_float4(a.x, a.y, b.x, b.y);
}

// ---- preprocessing ----

// Zero per-node degree counters; block 0 / warp 0 also detects index dtype
// (int64 nonneg values < 2^31 have zero high words).
__global__ void zero_detect_kernel(const unsigned int* __restrict__ w) {
    int i = blockIdx.x * blockDim.x + threadIdx.x;
    if (i < kNodes) g_count[i] = 0;
    if (blockIdx.x == 0 && threadIdx.x < 32) {
        unsigned int acc = 0;
        for (int k = threadIdx.x; k < 1024; k += 32) acc |= w[2 * k + 1];
        #pragma unroll
        for (int d = 1; d < 32; d <<= 1) acc |= __shfl_xor_sync(0xffffffffu, acc, d);
        if (threadIdx.x == 0) g_is_i32 = (acc != 0) ? 1 : 0;
    }
}

// Direct scatter into fixed-capacity per-target buckets.
// Entries are pre-scaled (src*32) so route's gather address is one IADD.
__global__ void fill_adj_kernel(const void* __restrict__ ei) {
    int e = blockIdx.x * blockDim.x + threadIdx.x;
    if (e >= kEdges) return;
    int s = load_idx(ei, e);
    int g = load_idx(ei, (long long)kEdges + e);
    int pos = atomicAdd(&g_count[g], 1);
    if (pos < kCap) g_adj[g * kCap + pos] = s * 32;
}

// ---- compute ----

// xc = l2norm_per_capsule(x); write fp32 + fp16 copies. One warp per node.
__global__ void __launch_bounds__(256) init_kernel(const float* __restrict__ x) {
    int gid  = blockIdx.x * blockDim.x + threadIdx.x;
    int node = gid >> 5;
    if (node >= kNodes) return;
    int t   = gid & 31;
    int idx = node * 32 + t;

    float4 v = reinterpret_cast<const float4*>(x)[idx];
    float ss = group4_sum(v.x * v.x + v.y * v.y + v.z * v.z + v.w * v.w);
    float s  = rsqrtf(fmaxf(ss, 1e-24f));
    v.x *= s; v.y *= s; v.z *= s; v.w *= s;
    g_xc[idx] = v;

    half2 a = __floats2half2_rn(v.x, v.y);
    half2 b = __floats2half2_rn(v.z, v.w);
    uint2 w;
    w.x = *reinterpret_cast<const unsigned int*>(&a);
    w.y = *reinterpret_cast<const unsigned int*>(&b);
    g_xch[idx] = w;
}

// One full routing iteration fused per node: warp n owns target node n.
// Lane t holds dims [4t,4t+4); capsule of lane t = t>>2.
// 2 independent edges per loop iteration (best-known structure, R12/R14).
// Micro-cuts: adjacency pre-scaled (addr = adj[i]+t, no IMAD); u pre-scaled by
// log2(e) so softmax exp is a bare exp2f (no per-edge FMUL); rsqrt norms.
// __launch_bounds__(256, 8): regs<=32 -> ~full occupancy (R14: occ 84.9%).
// No max-subtract: capsules are unit vectors => p in [-1,1].
template <bool FIRST, bool WRITE_OUT>
__global__ void __launch_bounds__(256, 8) route_kernel(float* __restrict__ out) {
    int gid  = blockIdx.x * blockDim.x + threadIdx.x;
    int node = gid >> 5;
    if (node >= kNodes) return;
    int t   = gid & 31;
    int idx = node * 32 + t;

    const float kLog2e = 1.4426950408889634f;
    float4 c = g_xc[idx];
    float4 u = FIRST ? c : g_u[idx];
    u.x *= kLog2e; u.y *= kLog2e; u.z *= kLog2e; u.w *= kLog2e;

    const int* adj = g_adj + node * kCap;
    int deg = min(g_count[node], kCap);

    float4 acc = make_float4(0.f, 0.f, 0.f, 0.f);
    int i = 0;
    for (; i + 2 <= deg; i += 2) {
        int a0 = adj[i];
        int a1 = adj[i + 1];
        float4 z0 = load_z_h(a0 + t);
        float4 z1 = load_z_h(a1 + t);

        float p0 = group4_sum(z0.x * u.x + z0.y * u.y + z0.z * u.z + z0.w * u.w);
        float p1 = group4_sum(z1.x * u.x + z1.y * u.y + z1.z * u.z + z1.w * u.w);
        float e0 = exp2f(p0);
        float e1 = exp2f(p1);
        float q0 = cap_sum(e0);
        float q1 = cap_sum(e1);
        float w0 = __fdividef(e0, q0);
        float w1 = __fdividef(e1, q1);

        acc.x += z0.x * w0 + z1.x * w1;
        acc.y += z0.y * w0 + z1.y * w1;
        acc.z += z0.z * w0 + z1.z * w1;
        acc.w += z0.w * w0 + z1.w * w1;
    }
    if (i < deg) {
        int a0 = adj[i];
        float4 z0 = load_z_h(a0 + t);
        float p0 = group4_sum(z0.x * u.x + z0.y * u.y + z0.z * u.z + z0.w * u.w);
        float e0 = exp2f(p0);
        float w0 = __fdividef(e0, cap_sum(e0));
        acc.x += z0.x * w0;
        acc.y += z0.y * w0;
        acc.z += z0.z * w0;
        acc.w += z0.w * w0;
    }

    // u_new = l2norm_per_capsule(acc + xc); only this warp touches row `node`.
    float4 v = make_float4(acc.x + c.x, acc.y + c.y, acc.z + c.z, acc.w + c.w);
    float ss = group4_sum(v.x * v.x + v.y * v.y + v.z * v.z + v.w * v.w);
    float s  = rsqrtf(fmaxf(ss, 1e-24f));
    v.x *= s; v.y *= s; v.z *= s; v.w *= s;

    if (WRITE_OUT) {
        reinterpret_cast<float4*>(out)[idx] = v;
    } else {
        g_u[idx] = v;
    }
}

}  // namespace

extern "C" void kernel_launch(void* const* d_in, const int* in_sizes, int n_in,
                              void* d_out, int out_size) {
    const float* x  = (const float*)d_in[0];
    const void*  ei = d_in[1];   // [2, E], int32 or int64 (detected on-device)
    float* out = (float*)d_out;

    const int nodeBlocks = (kNodes * 32 + 255) / 256;
    const int edgeBlocks = (kEdges + 255) / 256;

    zero_detect_kernel<<<(kNodes + 255) / 256, 256>>>((const unsigned int*)ei);
    fill_adj_kernel<<<edgeBlocks, 256>>>(ei);
    init_kernel<<<nodeBlocks, 256>>>(x);

    route_kernel<true,  false><<<nodeBlocks, 256>>>(nullptr);
    route_kernel<false, false><<<nodeBlocks, 256>>>(nullptr);
    route_kernel<false, true ><<<nodeBlocks, 256>>>(out);
}